// round 1
// baseline (speedup 1.0000x reference)
#include <cuda_runtime.h>
#include <math.h>

// Swin-V2 shifted-window MHA, fused per-window kernel.
// B=512, HIMG=WIMG=16, D=256, HEADS=8, HD=32, WIN=8, N=64, NW=4, SHIFT=4.
// One CTA (256 threads) per window; 2048 CTAs.

#define STR   260            // padded row stride in floats for 64x256 tiles
#define ASTR  68             // padded stride for 64x64 attn tile
#define BK    8              // K-tile depth for weight staging

// SMEM float offsets
#define OFF_SA   0           // x -> V        (64*260 = 16640)
#define OFF_SB   16640       // Q -> O        (16640)
#define OFF_SC   33280       // K             (16640)
#define OFF_WT   49920       // weight tile / bias table (2048)
#define OFF_ATT  51968       // attn probs    (64*68 = 4352)
#define OFF_GID  56320       // token group ids (64)
#define SMEM_FLOATS 56384    // 225536 bytes

__device__ float g_tab[225 * 8];   // 16*sigmoid(CPB-MLP table), [cell][head]

// ---------------------------------------------------------------------------
// Kernel 1: continuous position bias table. 225 blocks x 256 threads.
// ---------------------------------------------------------------------------
__global__ void cpb_kernel(const float* __restrict__ w1,   // [512,2]
                           const float* __restrict__ b1,   // [512]
                           const float* __restrict__ w2)   // [8,512]
{
    int t = threadIdx.x;
    int cell = blockIdx.x;            // 0..224
    int a = cell / 15, b = cell % 15;
    float ra = (a - 7) * (8.0f / 7.0f);
    float rb = (b - 7) * (8.0f / 7.0f);
    float va = (ra >= 0.f ? 1.f : -1.f) * log2f(fabsf(ra) + 1.f) * (1.f / 3.f);
    float vb = (rb >= 0.f ? 1.f : -1.f) * log2f(fabsf(rb) + 1.f) * (1.f / 3.f);

    int j1 = t, j2 = t + 256;
    float h1 = fmaxf(va * w1[j1 * 2] + vb * w1[j1 * 2 + 1] + b1[j1], 0.f);
    float h2 = fmaxf(va * w1[j2 * 2] + vb * w1[j2 * 2 + 1] + b1[j2], 0.f);

    float p[8];
#pragma unroll
    for (int h = 0; h < 8; h++)
        p[h] = h1 * w2[h * 512 + j1] + h2 * w2[h * 512 + j2];
#pragma unroll
    for (int h = 0; h < 8; h++)
#pragma unroll
        for (int off = 16; off; off >>= 1)
            p[h] += __shfl_xor_sync(0xffffffffu, p[h], off);

    __shared__ float ws[8][8];
    int warp = t >> 5, lane = t & 31;
    if (lane == 0) {
#pragma unroll
        for (int h = 0; h < 8; h++) ws[warp][h] = p[h];
    }
    __syncthreads();
    if (t < 8) {
        float s = 0.f;
#pragma unroll
        for (int w = 0; w < 8; w++) s += ws[w][t];
        g_tab[cell * 8 + t] = 16.f / (1.f + expf(-s));
    }
}

// ---------------------------------------------------------------------------
// 64x256 @ 256x256^T GEMM core: A in smem (rows stride STR), W global row-major
// [out j][in k], staged into WT as [kk][j]. acc[ri][jj] for rows tr*8+ri,
// cols tc+32*jj. Entry/exit synchronized.
// ---------------------------------------------------------------------------
__device__ __forceinline__ void gemm64(const float* __restrict__ srcS,
                                       const float* __restrict__ w,
                                       float* __restrict__ wt,
                                       float acc[8][8], int tr, int tc, int t)
{
#pragma unroll 1
    for (int k0 = 0; k0 < 256; k0 += BK) {
        // stage W[j][k0..k0+7] -> wt[kk][j], coalesced float4 global loads
#pragma unroll
        for (int i = 0; i < 2; i++) {
            int f4 = i * 256 + t;
            int j = f4 >> 1, q = f4 & 1;
            float4 v = *reinterpret_cast<const float4*>(&w[j * 256 + k0 + q * 4]);
            wt[(q * 4 + 0) * 256 + j] = v.x;
            wt[(q * 4 + 1) * 256 + j] = v.y;
            wt[(q * 4 + 2) * 256 + j] = v.z;
            wt[(q * 4 + 3) * 256 + j] = v.w;
        }
        __syncthreads();
#pragma unroll
        for (int kk = 0; kk < BK; kk++) {
            float a[8], bb[8];
#pragma unroll
            for (int ri = 0; ri < 8; ri++) a[ri] = srcS[(tr * 8 + ri) * STR + k0 + kk];
#pragma unroll
            for (int jj = 0; jj < 8; jj++) bb[jj] = wt[kk * 256 + tc + 32 * jj];
#pragma unroll
            for (int ri = 0; ri < 8; ri++)
#pragma unroll
                for (int jj = 0; jj < 8; jj++)
                    acc[ri][jj] = fmaf(a[ri], bb[jj], acc[ri][jj]);
        }
        __syncthreads();
    }
}

// ---------------------------------------------------------------------------
// Main fused kernel. grid = 2048 (b*4 + wh*2 + ww), block = 256.
// ---------------------------------------------------------------------------
__global__ __launch_bounds__(256, 1)
void swin_kernel(const float* __restrict__ img,
                 const float* __restrict__ wq, const float* __restrict__ bq,
                 const float* __restrict__ wk, const float* __restrict__ bk,
                 const float* __restrict__ wv, const float* __restrict__ bv,
                 const float* __restrict__ wo, const float* __restrict__ bo,
                 const float* __restrict__ logit_scale,
                 float* __restrict__ out)
{
    extern __shared__ float sm[];
    float* SA  = sm + OFF_SA;   // x, later V
    float* SB  = sm + OFF_SB;   // Q, later O
    float* SC  = sm + OFF_SC;   // K
    float* WT  = sm + OFF_WT;   // weight tile / bias table
    float* ATT = sm + OFF_ATT;  // attn probs
    int*   GID = (int*)(sm + OFF_GID);

    const int t  = threadIdx.x;
    const int tr = t >> 5, tc = t & 31;
    const int blk = blockIdx.x;
    const int b   = blk >> 2;
    const int wh  = (blk >> 1) & 1, ww = blk & 1;

    // ---- load shifted window: x[tok][d] = img[(wh*8+r-4)&15][(ww*8+c-4)&15][d]
    const float* imgb = img + (size_t)b * (16 * 16 * 256);
#pragma unroll
    for (int i = 0; i < 16; i++) {
        int f = i * 256 + t;            // float4 index
        int tok = f >> 6, c4 = f & 63;
        int r = tok >> 3, c = tok & 7;
        int ih = (wh * 8 + r + 12) & 15;
        int iw = (ww * 8 + c + 12) & 15;
        float4 v = *reinterpret_cast<const float4*>(&imgb[(ih * 16 + iw) * 256 + c4 * 4]);
        *reinterpret_cast<float4*>(&SA[tok * STR + c4 * 4]) = v;
    }
    if (t < 64) {  // token shift-mask group ids
        int r = t >> 3, c = t & 7;
        int gh = wh * 8 + r, gw = ww * 8 + c;
        int hg = (gh < 8) ? 0 : (gh < 12 ? 1 : 2);
        int wg = (gw < 8) ? 0 : (gw < 12 ? 1 : 2);
        GID[t] = hg * 3 + wg;
    }
    __syncthreads();

    float acc[8][8];

    // ---- Q = x @ wq^T + bq -> SB
#pragma unroll
    for (int ri = 0; ri < 8; ri++)
#pragma unroll
        for (int jj = 0; jj < 8; jj++) acc[ri][jj] = 0.f;
    gemm64(SA, wq, WT, acc, tr, tc, t);
    {
        float bb[8];
#pragma unroll
        for (int jj = 0; jj < 8; jj++) bb[jj] = bq[tc + 32 * jj];
#pragma unroll
        for (int ri = 0; ri < 8; ri++)
#pragma unroll
            for (int jj = 0; jj < 8; jj++)
                SB[(tr * 8 + ri) * STR + tc + 32 * jj] = acc[ri][jj] + bb[jj];
    }

    // ---- K = x @ wk^T + bk -> SC
#pragma unroll
    for (int ri = 0; ri < 8; ri++)
#pragma unroll
        for (int jj = 0; jj < 8; jj++) acc[ri][jj] = 0.f;
    gemm64(SA, wk, WT, acc, tr, tc, t);
    {
        float bb[8];
#pragma unroll
        for (int jj = 0; jj < 8; jj++) bb[jj] = bk[tc + 32 * jj];
#pragma unroll
        for (int ri = 0; ri < 8; ri++)
#pragma unroll
            for (int jj = 0; jj < 8; jj++)
                SC[(tr * 8 + ri) * STR + tc + 32 * jj] = acc[ri][jj] + bb[jj];
    }

    // ---- V = x @ wv^T + bv -> overwrite SA (compute in regs first)
#pragma unroll
    for (int ri = 0; ri < 8; ri++)
#pragma unroll
        for (int jj = 0; jj < 8; jj++) acc[ri][jj] = 0.f;
    gemm64(SA, wv, WT, acc, tr, tc, t);   // exits with all SA reads complete
    {
        float bb[8];
#pragma unroll
        for (int jj = 0; jj < 8; jj++) bb[jj] = bv[tc + 32 * jj];
#pragma unroll
        for (int ri = 0; ri < 8; ri++)
#pragma unroll
            for (int jj = 0; jj < 8; jj++)
                SA[(tr * 8 + ri) * STR + tc + 32 * jj] = acc[ri][jj] + bb[jj];
    }
    __syncthreads();

    // ---- normalize Q (fold per-head scale in) and K, per (row, head)
#pragma unroll 1
    for (int p = t; p < 1024; p += 256) {
        int mat = p >> 9;           // 0 = Q, 1 = K
        int h   = (p >> 6) & 7;
        int n   = p & 63;
        float* row = (mat ? SC : SB) + n * STR + h * 32;
        float ss = 0.f;
#pragma unroll
        for (int k = 0; k < 32; k++) ss += row[k] * row[k];
        float sc = 1.f / fmaxf(sqrtf(ss), 1e-12f);
        if (mat == 0) sc *= expf(fminf(logit_scale[h], 4.6051702f)); // ln(100)
#pragma unroll
        for (int k = 0; k < 32; k++) row[k] *= sc;
    }
    // stash bias table into (idle) weight-tile smem
    for (int i = t; i < 1800; i += 256) WT[i] = g_tab[i];
    __syncthreads();

    // ---- attention, head by head. n = t>>2; m = (t&3) + 4*mm
    const int n  = t >> 2;
    const int mg = t & 3;
    const int rn = n >> 3, cn = n & 7;
    const int gidn = GID[n];
    const float NEG_INF = __int_as_float(0xff800000);

#pragma unroll 1
    for (int h = 0; h < 8; h++) {
        float qreg[32];
#pragma unroll
        for (int k = 0; k < 32; k++) qreg[k] = SB[n * STR + h * 32 + k];

        float lg[16];
#pragma unroll
        for (int mm = 0; mm < 16; mm++) {
            int m = mg + 4 * mm;
            float d = 0.f;
#pragma unroll
            for (int k = 0; k < 32; k++)
                d = fmaf(qreg[k], SC[m * STR + h * 32 + k], d);
            int gidm = GID[m];
            int rm = m >> 3, cm = m & 7;
            int tix = ((rn - rm + 7) * 15 + (cn - cm + 7)) * 8 + h;
            lg[mm] = (gidn == gidm) ? (d + WT[tix]) : NEG_INF;
        }
        // softmax over row n (quad of lanes)
        float mx = NEG_INF;
#pragma unroll
        for (int mm = 0; mm < 16; mm++) mx = fmaxf(mx, lg[mm]);
        mx = fmaxf(mx, __shfl_xor_sync(0xffffffffu, mx, 1));
        mx = fmaxf(mx, __shfl_xor_sync(0xffffffffu, mx, 2));
        float s = 0.f;
#pragma unroll
        for (int mm = 0; mm < 16; mm++) { lg[mm] = expf(lg[mm] - mx); s += lg[mm]; }
        s += __shfl_xor_sync(0xffffffffu, s, 1);
        s += __shfl_xor_sync(0xffffffffu, s, 2);
        float inv = 1.f / s;
#pragma unroll
        for (int mm = 0; mm < 16; mm++) ATT[n * ASTR + mg + 4 * mm] = lg[mm] * inv;
        __syncthreads();   // also guarantees all qreg loads done -> Q cols h*32.. free

        // o_h = attn @ V_h  -> write into freed Q columns (SB becomes O)
        {
            int cb = mg * 8;
            float o[8];
#pragma unroll
            for (int j = 0; j < 8; j++) o[j] = 0.f;
#pragma unroll 1
            for (int m = 0; m < 64; m++) {
                float a = ATT[n * ASTR + m];
#pragma unroll
                for (int j = 0; j < 8; j++)
                    o[j] = fmaf(a, SA[m * STR + h * 32 + cb + j], o[j]);
            }
#pragma unroll
            for (int j = 0; j < 8; j++) SB[n * STR + h * 32 + cb + j] = o[j];
        }
        __syncthreads();   // ATT reuse next head; SB(O) writes ordered
    }

    // ---- Z = O @ wo^T + bo, scattered to output with inverse cyclic shift
#pragma unroll
    for (int ri = 0; ri < 8; ri++)
#pragma unroll
        for (int jj = 0; jj < 8; jj++) acc[ri][jj] = 0.f;
    gemm64(SB, wo, WT, acc, tr, tc, t);
    {
        float bb[8];
#pragma unroll
        for (int jj = 0; jj < 8; jj++) bb[jj] = bo[tc + 32 * jj];
#pragma unroll
        for (int ri = 0; ri < 8; ri++) {
            int tok = tr * 8 + ri;
            int rr = tok >> 3, cc = tok & 7;
            int oh = (wh * 8 + rr + 12) & 15;
            int ow = (ww * 8 + cc + 12) & 15;
            float* dst = out + ((size_t)(b * 16 + oh) * 16 + ow) * 256;
#pragma unroll
            for (int jj = 0; jj < 8; jj++)
                dst[tc + 32 * jj] = acc[ri][jj] + bb[jj];
        }
    }
}

// ---------------------------------------------------------------------------
extern "C" void kernel_launch(void* const* d_in, const int* in_sizes, int n_in,
                              void* d_out, int out_size)
{
    const float* img = (const float*)d_in[0];
    const float* wq  = (const float*)d_in[1];
    const float* bq  = (const float*)d_in[2];
    const float* wk  = (const float*)d_in[3];
    const float* bk  = (const float*)d_in[4];
    const float* wv  = (const float*)d_in[5];
    const float* bv  = (const float*)d_in[6];
    const float* wo  = (const float*)d_in[7];
    const float* bo  = (const float*)d_in[8];
    const float* ls  = (const float*)d_in[9];
    const float* cw1 = (const float*)d_in[10];
    const float* cb1 = (const float*)d_in[11];
    const float* cw2 = (const float*)d_in[12];
    (void)in_sizes; (void)n_in; (void)out_size;

    cudaFuncSetAttribute(swin_kernel,
                         cudaFuncAttributeMaxDynamicSharedMemorySize,
                         SMEM_FLOATS * 4);

    cpb_kernel<<<225, 256>>>(cw1, cb1, cw2);
    swin_kernel<<<2048, 256, SMEM_FLOATS * 4>>>(img, wq, bq, wk, bk, wv, bv,
                                                wo, bo, ls, (float*)d_out);
}

// round 2
// speedup vs baseline: 1.0005x; 1.0005x over previous
#include <cuda_runtime.h>
#include <math.h>

// Swin-V2 shifted-window MHA, fused per-window kernel.
// B=512, HIMG=WIMG=16, D=256, HEADS=8, HD=32, WIN=8, N=64, NW=4, SHIFT=4.
// One CTA (256 threads) per window; 2048 CTAs.

#define STR   260            // padded row stride in floats for 64x256 tiles
#define ASTR  68             // padded stride for 64x64 attn tile
#define BK    8              // K-tile depth for weight staging

// SMEM float offsets
#define OFF_SA   0           // x -> V        (64*260 = 16640)
#define OFF_SB   16640       // Q -> O        (16640)
#define OFF_SC   33280       // K             (16640)
#define OFF_WT   49920       // weight tile / bias table (2048)
#define OFF_ATT  51968       // attn probs    (64*68 = 4352)
#define OFF_GID  56320       // token group ids (64)
#define SMEM_FLOATS 56384    // 225536 bytes

__device__ float g_tab[225 * 8];   // 16*sigmoid(CPB-MLP table), [cell][head]

// ---------------------------------------------------------------------------
// Kernel 1: continuous position bias table. 225 blocks x 256 threads.
// ---------------------------------------------------------------------------
__global__ void cpb_kernel(const float* __restrict__ w1,   // [512,2]
                           const float* __restrict__ b1,   // [512]
                           const float* __restrict__ w2)   // [8,512]
{
    int t = threadIdx.x;
    int cell = blockIdx.x;            // 0..224
    int a = cell / 15, b = cell % 15;
    float ra = (a - 7) * (8.0f / 7.0f);
    float rb = (b - 7) * (8.0f / 7.0f);
    float va = (ra >= 0.f ? 1.f : -1.f) * log2f(fabsf(ra) + 1.f) * (1.f / 3.f);
    float vb = (rb >= 0.f ? 1.f : -1.f) * log2f(fabsf(rb) + 1.f) * (1.f / 3.f);

    int j1 = t, j2 = t + 256;
    float h1 = fmaxf(va * w1[j1 * 2] + vb * w1[j1 * 2 + 1] + b1[j1], 0.f);
    float h2 = fmaxf(va * w1[j2 * 2] + vb * w1[j2 * 2 + 1] + b1[j2], 0.f);

    float p[8];
#pragma unroll
    for (int h = 0; h < 8; h++)
        p[h] = h1 * w2[h * 512 + j1] + h2 * w2[h * 512 + j2];
#pragma unroll
    for (int h = 0; h < 8; h++)
#pragma unroll
        for (int off = 16; off; off >>= 1)
            p[h] += __shfl_xor_sync(0xffffffffu, p[h], off);

    __shared__ float ws[8][8];
    int warp = t >> 5, lane = t & 31;
    if (lane == 0) {
#pragma unroll
        for (int h = 0; h < 8; h++) ws[warp][h] = p[h];
    }
    __syncthreads();
    if (t < 8) {
        float s = 0.f;
#pragma unroll
        for (int w = 0; w < 8; w++) s += ws[w][t];
        g_tab[cell * 8 + t] = 16.f / (1.f + expf(-s));
    }
}

// ---------------------------------------------------------------------------
// 64x256 @ 256x256^T GEMM core: A in smem (rows stride STR), W global row-major
// [out j][in k], staged into WT as [kk][j]. acc[ri][jj] for rows tr*8+ri,
// cols tc+32*jj. Entry/exit synchronized.
// ---------------------------------------------------------------------------
__device__ __forceinline__ void gemm64(const float* __restrict__ srcS,
                                       const float* __restrict__ w,
                                       float* __restrict__ wt,
                                       float acc[8][8], int tr, int tc, int t)
{
#pragma unroll 1
    for (int k0 = 0; k0 < 256; k0 += BK) {
        // stage W[j][k0..k0+7] -> wt[kk][j], coalesced float4 global loads
#pragma unroll
        for (int i = 0; i < 2; i++) {
            int f4 = i * 256 + t;
            int j = f4 >> 1, q = f4 & 1;
            float4 v = *reinterpret_cast<const float4*>(&w[j * 256 + k0 + q * 4]);
            wt[(q * 4 + 0) * 256 + j] = v.x;
            wt[(q * 4 + 1) * 256 + j] = v.y;
            wt[(q * 4 + 2) * 256 + j] = v.z;
            wt[(q * 4 + 3) * 256 + j] = v.w;
        }
        __syncthreads();
#pragma unroll
        for (int kk = 0; kk < BK; kk++) {
            float a[8], bb[8];
#pragma unroll
            for (int ri = 0; ri < 8; ri++) a[ri] = srcS[(tr * 8 + ri) * STR + k0 + kk];
#pragma unroll
            for (int jj = 0; jj < 8; jj++) bb[jj] = wt[kk * 256 + tc + 32 * jj];
#pragma unroll
            for (int ri = 0; ri < 8; ri++)
#pragma unroll
                for (int jj = 0; jj < 8; jj++)
                    acc[ri][jj] = fmaf(a[ri], bb[jj], acc[ri][jj]);
        }
        __syncthreads();
    }
}

// ---------------------------------------------------------------------------
// Main fused kernel. grid = 2048 (b*4 + wh*2 + ww), block = 256.
// ---------------------------------------------------------------------------
__global__ __launch_bounds__(256, 1)
void swin_kernel(const float* __restrict__ img,
                 const float* __restrict__ wq, const float* __restrict__ bq,
                 const float* __restrict__ wk, const float* __restrict__ bk,
                 const float* __restrict__ wv, const float* __restrict__ bv,
                 const float* __restrict__ wo, const float* __restrict__ bo,
                 const float* __restrict__ logit_scale,
                 float* __restrict__ out)
{
    extern __shared__ float sm[];
    float* SA  = sm + OFF_SA;   // x, later V
    float* SB  = sm + OFF_SB;   // Q, later O
    float* SC  = sm + OFF_SC;   // K
    float* WT  = sm + OFF_WT;   // weight tile / bias table
    float* ATT = sm + OFF_ATT;  // attn probs
    int*   GID = (int*)(sm + OFF_GID);

    const int t  = threadIdx.x;
    const int tr = t >> 5, tc = t & 31;
    const int blk = blockIdx.x;
    const int b   = blk >> 2;
    const int wh  = (blk >> 1) & 1, ww = blk & 1;

    // ---- load shifted window: x[tok][d] = img[(wh*8+r-4)&15][(ww*8+c-4)&15][d]
    const float* imgb = img + (size_t)b * (16 * 16 * 256);
#pragma unroll
    for (int i = 0; i < 16; i++) {
        int f = i * 256 + t;            // float4 index
        int tok = f >> 6, c4 = f & 63;
        int r = tok >> 3, c = tok & 7;
        int ih = (wh * 8 + r + 12) & 15;
        int iw = (ww * 8 + c + 12) & 15;
        float4 v = *reinterpret_cast<const float4*>(&imgb[(ih * 16 + iw) * 256 + c4 * 4]);
        *reinterpret_cast<float4*>(&SA[tok * STR + c4 * 4]) = v;
    }
    if (t < 64) {  // token shift-mask group ids
        int r = t >> 3, c = t & 7;
        int gh = wh * 8 + r, gw = ww * 8 + c;
        int hg = (gh < 8) ? 0 : (gh < 12 ? 1 : 2);
        int wg = (gw < 8) ? 0 : (gw < 12 ? 1 : 2);
        GID[t] = hg * 3 + wg;
    }
    __syncthreads();

    float acc[8][8];

    // ---- Q = x @ wq^T + bq -> SB
#pragma unroll
    for (int ri = 0; ri < 8; ri++)
#pragma unroll
        for (int jj = 0; jj < 8; jj++) acc[ri][jj] = 0.f;
    gemm64(SA, wq, WT, acc, tr, tc, t);
    {
        float bb[8];
#pragma unroll
        for (int jj = 0; jj < 8; jj++) bb[jj] = bq[tc + 32 * jj];
#pragma unroll
        for (int ri = 0; ri < 8; ri++)
#pragma unroll
            for (int jj = 0; jj < 8; jj++)
                SB[(tr * 8 + ri) * STR + tc + 32 * jj] = acc[ri][jj] + bb[jj];
    }

    // ---- K = x @ wk^T + bk -> SC
#pragma unroll
    for (int ri = 0; ri < 8; ri++)
#pragma unroll
        for (int jj = 0; jj < 8; jj++) acc[ri][jj] = 0.f;
    gemm64(SA, wk, WT, acc, tr, tc, t);
    {
        float bb[8];
#pragma unroll
        for (int jj = 0; jj < 8; jj++) bb[jj] = bk[tc + 32 * jj];
#pragma unroll
        for (int ri = 0; ri < 8; ri++)
#pragma unroll
            for (int jj = 0; jj < 8; jj++)
                SC[(tr * 8 + ri) * STR + tc + 32 * jj] = acc[ri][jj] + bb[jj];
    }

    // ---- V = x @ wv^T + bv -> overwrite SA (compute in regs first)
#pragma unroll
    for (int ri = 0; ri < 8; ri++)
#pragma unroll
        for (int jj = 0; jj < 8; jj++) acc[ri][jj] = 0.f;
    gemm64(SA, wv, WT, acc, tr, tc, t);   // exits with all SA reads complete
    {
        float bb[8];
#pragma unroll
        for (int jj = 0; jj < 8; jj++) bb[jj] = bv[tc + 32 * jj];
#pragma unroll
        for (int ri = 0; ri < 8; ri++)
#pragma unroll
            for (int jj = 0; jj < 8; jj++)
                SA[(tr * 8 + ri) * STR + tc + 32 * jj] = acc[ri][jj] + bb[jj];
    }
    __syncthreads();

    // ---- normalize Q (fold per-head scale in) and K, per (row, head)
#pragma unroll 1
    for (int p = t; p < 1024; p += 256) {
        int mat = p >> 9;           // 0 = Q, 1 = K
        int h   = (p >> 6) & 7;
        int n   = p & 63;
        float* row = (mat ? SC : SB) + n * STR + h * 32;
        float ss = 0.f;
#pragma unroll
        for (int k = 0; k < 32; k++) ss += row[k] * row[k];
        float sc = 1.f / fmaxf(sqrtf(ss), 1e-12f);
        if (mat == 0) sc *= expf(fminf(logit_scale[h], 4.6051702f)); // ln(100)
#pragma unroll
        for (int k = 0; k < 32; k++) row[k] *= sc;
    }
    // stash bias table into (idle) weight-tile smem
    for (int i = t; i < 1800; i += 256) WT[i] = g_tab[i];
    __syncthreads();

    // ---- attention, head by head. n = t>>2; m = (t&3) + 4*mm
    const int n  = t >> 2;
    const int mg = t & 3;
    const int rn = n >> 3, cn = n & 7;
    const int gidn = GID[n];
    const float NEG_INF = __int_as_float(0xff800000);

#pragma unroll 1
    for (int h = 0; h < 8; h++) {
        float qreg[32];
#pragma unroll
        for (int k = 0; k < 32; k++) qreg[k] = SB[n * STR + h * 32 + k];

        float lg[16];
#pragma unroll
        for (int mm = 0; mm < 16; mm++) {
            int m = mg + 4 * mm;
            float d = 0.f;
#pragma unroll
            for (int k = 0; k < 32; k++)
                d = fmaf(qreg[k], SC[m * STR + h * 32 + k], d);
            int gidm = GID[m];
            int rm = m >> 3, cm = m & 7;
            int tix = ((rn - rm + 7) * 15 + (cn - cm + 7)) * 8 + h;
            lg[mm] = (gidn == gidm) ? (d + WT[tix]) : NEG_INF;
        }
        // softmax over row n (quad of lanes)
        float mx = NEG_INF;
#pragma unroll
        for (int mm = 0; mm < 16; mm++) mx = fmaxf(mx, lg[mm]);
        mx = fmaxf(mx, __shfl_xor_sync(0xffffffffu, mx, 1));
        mx = fmaxf(mx, __shfl_xor_sync(0xffffffffu, mx, 2));
        float s = 0.f;
#pragma unroll
        for (int mm = 0; mm < 16; mm++) { lg[mm] = expf(lg[mm] - mx); s += lg[mm]; }
        s += __shfl_xor_sync(0xffffffffu, s, 1);
        s += __shfl_xor_sync(0xffffffffu, s, 2);
        float inv = 1.f / s;
#pragma unroll
        for (int mm = 0; mm < 16; mm++) ATT[n * ASTR + mg + 4 * mm] = lg[mm] * inv;
        __syncthreads();   // also guarantees all qreg loads done -> Q cols h*32.. free

        // o_h = attn @ V_h  -> write into freed Q columns (SB becomes O)
        {
            int cb = mg * 8;
            float o[8];
#pragma unroll
            for (int j = 0; j < 8; j++) o[j] = 0.f;
#pragma unroll 1
            for (int m = 0; m < 64; m++) {
                float a = ATT[n * ASTR + m];
#pragma unroll
                for (int j = 0; j < 8; j++)
                    o[j] = fmaf(a, SA[m * STR + h * 32 + cb + j], o[j]);
            }
#pragma unroll
            for (int j = 0; j < 8; j++) SB[n * STR + h * 32 + cb + j] = o[j];
        }
        __syncthreads();   // ATT reuse next head; SB(O) writes ordered
    }

    // ---- Z = O @ wo^T + bo, scattered to output with inverse cyclic shift
#pragma unroll
    for (int ri = 0; ri < 8; ri++)
#pragma unroll
        for (int jj = 0; jj < 8; jj++) acc[ri][jj] = 0.f;
    gemm64(SB, wo, WT, acc, tr, tc, t);
    {
        float bb[8];
#pragma unroll
        for (int jj = 0; jj < 8; jj++) bb[jj] = bo[tc + 32 * jj];
#pragma unroll
        for (int ri = 0; ri < 8; ri++) {
            int tok = tr * 8 + ri;
            int rr = tok >> 3, cc = tok & 7;
            int oh = (wh * 8 + rr + 12) & 15;
            int ow = (ww * 8 + cc + 12) & 15;
            float* dst = out + ((size_t)(b * 16 + oh) * 16 + ow) * 256;
#pragma unroll
            for (int jj = 0; jj < 8; jj++)
                dst[tc + 32 * jj] = acc[ri][jj] + bb[jj];
        }
    }
}

// ---------------------------------------------------------------------------
extern "C" void kernel_launch(void* const* d_in, const int* in_sizes, int n_in,
                              void* d_out, int out_size)
{
    const float* img = (const float*)d_in[0];
    const float* wq  = (const float*)d_in[1];
    const float* bq  = (const float*)d_in[2];
    const float* wk  = (const float*)d_in[3];
    const float* bk  = (const float*)d_in[4];
    const float* wv  = (const float*)d_in[5];
    const float* bv  = (const float*)d_in[6];
    const float* wo  = (const float*)d_in[7];
    const float* bo  = (const float*)d_in[8];
    const float* ls  = (const float*)d_in[9];
    const float* cw1 = (const float*)d_in[10];
    const float* cb1 = (const float*)d_in[11];
    const float* cw2 = (const float*)d_in[12];
    (void)in_sizes; (void)n_in; (void)out_size;

    cudaFuncSetAttribute(swin_kernel,
                         cudaFuncAttributeMaxDynamicSharedMemorySize,
                         SMEM_FLOATS * 4);

    cpb_kernel<<<225, 256>>>(cw1, cb1, cw2);
    swin_kernel<<<2048, 256, SMEM_FLOATS * 4>>>(img, wq, bq, wk, bk, wv, bv,
                                                wo, bo, ls, (float*)d_out);
}

// round 3
// speedup vs baseline: 1.7343x; 1.7334x over previous
#include <cuda_runtime.h>
#include <cuda_bf16.h>
#include <math.h>
#include <stdint.h>

// Swin-V2 shifted-window MHA, fused per-window kernel with split-bf16 MMA GEMMs.
// B=512, HIMG=WIMG=16, D=256, HEADS=8, HD=32, WIN=8, N=64, NW=4, SHIFT=4.
// One CTA (256 threads = 8 warps) per window; 2048 CTAs.

#define XSTR 132   // u32 (bf16-pair) row stride for split tiles (bank = lane, conflict-free)
#define FSTR 260   // fp32 row stride for Q/K/V/O tiles
#define WSTR 12    // u32 row stride for staged weight tiles (8 data + 4 pad)

// SMEM layout in 4-byte units
#define OFF_XH   0            // x hi pairs  64x132          (8448)   } R0: later V fp32 (16640)
#define OFF_XL   8448         // x lo pairs                  (8448)   }
#define OFF_Q    16896        // Q fp32 -> O fp32            (16640)
#define OFF_K    33536        // K fp32                      (16640)  } R2: later OH/OL
#define OFF_OH   33536        //   O hi pairs (8448)
#define OFF_OL   41984        //   O lo pairs (8448)
#define OFF_WTH  50432        // staged W hi tile 256x12     (3072)  / bias table (1800)
#define OFF_WTL  53504        // staged W lo tile            (3072)
#define OFF_GID  56576        // token group ids             (64)
#define SMEM_U32 56640        // 226560 bytes

__device__ uint32_t g_wh[4 * 256 * 128];  // pre-split weights: hi bf16 pairs, [w][n][kpair]
__device__ uint32_t g_wl[4 * 256 * 128];  // lo bf16 pairs
__device__ float    g_tab[225 * 8];       // 16*sigmoid(CPB-MLP table), [cell][head]

// ---------------------------------------------------------------------------
__device__ __forceinline__ uint32_t pack2(__nv_bfloat16 a, __nv_bfloat16 b) {
    return (uint32_t)__bfloat16_as_ushort(a) | ((uint32_t)__bfloat16_as_ushort(b) << 16);
}
__device__ __forceinline__ void split2(float x, float y, uint32_t& h, uint32_t& l) {
    __nv_bfloat16 hx = __float2bfloat16_rn(x), hy = __float2bfloat16_rn(y);
    float rx = x - __bfloat162float(hx), ry = y - __bfloat162float(hy);
    h = pack2(hx, hy);
    l = pack2(__float2bfloat16_rn(rx), __float2bfloat16_rn(ry));
}

#define MMA16816(C, A0, A1, A2, A3, B0, B1)                                   \
    asm volatile("mma.sync.aligned.m16n8k16.row.col.f32.bf16.bf16.f32 "       \
                 "{%0,%1,%2,%3}, {%4,%5,%6,%7}, {%8,%9}, {%0,%1,%2,%3};"      \
                 : "+f"(C[0]), "+f"(C[1]), "+f"(C[2]), "+f"(C[3])             \
                 : "r"(A0), "r"(A1), "r"(A2), "r"(A3), "r"(B0), "r"(B1))

// ---------------------------------------------------------------------------
// Kernel 1: continuous position bias table. 225 blocks x 256 threads.
// ---------------------------------------------------------------------------
__global__ void cpb_kernel(const float* __restrict__ w1,   // [512,2]
                           const float* __restrict__ b1,   // [512]
                           const float* __restrict__ w2)   // [8,512]
{
    int t = threadIdx.x;
    int cell = blockIdx.x;            // 0..224
    int a = cell / 15, b = cell % 15;
    float ra = (a - 7) * (8.0f / 7.0f);
    float rb = (b - 7) * (8.0f / 7.0f);
    float va = (ra >= 0.f ? 1.f : -1.f) * log2f(fabsf(ra) + 1.f) * (1.f / 3.f);
    float vb = (rb >= 0.f ? 1.f : -1.f) * log2f(fabsf(rb) + 1.f) * (1.f / 3.f);

    int j1 = t, j2 = t + 256;
    float h1 = fmaxf(va * w1[j1 * 2] + vb * w1[j1 * 2 + 1] + b1[j1], 0.f);
    float h2 = fmaxf(va * w1[j2 * 2] + vb * w1[j2 * 2 + 1] + b1[j2], 0.f);

    float p[8];
#pragma unroll
    for (int h = 0; h < 8; h++)
        p[h] = h1 * w2[h * 512 + j1] + h2 * w2[h * 512 + j2];
#pragma unroll
    for (int h = 0; h < 8; h++)
#pragma unroll
        for (int off = 16; off; off >>= 1)
            p[h] += __shfl_xor_sync(0xffffffffu, p[h], off);

    __shared__ float ws[8][8];
    int warp = t >> 5, lane = t & 31;
    if (lane == 0) {
#pragma unroll
        for (int h = 0; h < 8; h++) ws[warp][h] = p[h];
    }
    __syncthreads();
    if (t < 8) {
        float s = 0.f;
#pragma unroll
        for (int w = 0; w < 8; w++) s += ws[w][t];
        g_tab[cell * 8 + t] = 16.f / (1.f + expf(-s));
    }
}

// ---------------------------------------------------------------------------
// Kernel 2: pre-split weights into bf16 hi/lo pair tables.
// grid = 64 (4 weights x 16 segments), 256 threads.
// ---------------------------------------------------------------------------
__global__ void wsplit_kernel(const float* __restrict__ wq,
                              const float* __restrict__ wk,
                              const float* __restrict__ wv,
                              const float* __restrict__ wo)
{
    const float* ws[4] = {wq, wk, wv, wo};
    int t = threadIdx.x;
    int wsel = blockIdx.x >> 4;
    int seg  = blockIdx.x & 15;
    const float* w = ws[wsel];
    uint32_t* gh = g_wh + wsel * 32768;
    uint32_t* gl = g_wl + wsel * 32768;
#pragma unroll
    for (int i = 0; i < 4; i++) {
        int f4 = seg * 1024 + i * 256 + t;    // float4 index in [0,16384)
        int n = f4 >> 6, q = f4 & 63;
        float4 v = *reinterpret_cast<const float4*>(&w[n * 256 + q * 4]);
        uint32_t h0, l0, h1, l1;
        split2(v.x, v.y, h0, l0);
        split2(v.z, v.w, h1, l1);
        gh[n * 128 + 2 * q]     = h0;
        gh[n * 128 + 2 * q + 1] = h1;
        gl[n * 128 + 2 * q]     = l0;
        gl[n * 128 + 2 * q + 1] = l1;
    }
}

// ---------------------------------------------------------------------------
// Split-bf16 64x256 @ 256x256^T GEMM via mma.sync m16n8k16.
// A (split pairs) in smem at xh/xl; W pre-split in global gwh/gwl; staged per
// 16-wide k-chunk into wtH/wtL. acc[16][4] = 16x128 per warp
// (rows warpM*16 + gid/+8, cols warpN*128 + nf*8 + 2*tg/+1).
// Ends with __syncthreads (A reads and WT reads complete).
// ---------------------------------------------------------------------------
__device__ __forceinline__ void gemm_mma(
    const uint32_t* __restrict__ xh, const uint32_t* __restrict__ xl,
    const uint32_t* __restrict__ gwh, const uint32_t* __restrict__ gwl,
    uint32_t* __restrict__ wtH, uint32_t* __restrict__ wtL,
    float acc[16][4], int warpM, int warpN, int lane, int t)
{
#pragma unroll
    for (int nf = 0; nf < 16; nf++)
#pragma unroll
        for (int j = 0; j < 4; j++) acc[nf][j] = 0.f;

    const int gid = lane >> 2, tg = lane & 3;
    const uint32_t* xha = xh + (warpM * 16 + gid) * XSTR + tg;
    const uint32_t* xla = xl + (warpM * 16 + gid) * XSTR + tg;

    // per-thread staging registers (software pipeline over k-chunks)
    uint4 rh[2], rl[2];
    const int n0 = (t + 0)   >> 1, q0 = (t + 0)   & 1;
    const int n1 = (t + 256) >> 1, q1 = (t + 256) & 1;
    rh[0] = *reinterpret_cast<const uint4*>(gwh + n0 * 128 + q0 * 4);
    rh[1] = *reinterpret_cast<const uint4*>(gwh + n1 * 128 + q1 * 4);
    rl[0] = *reinterpret_cast<const uint4*>(gwl + n0 * 128 + q0 * 4);
    rl[1] = *reinterpret_cast<const uint4*>(gwl + n1 * 128 + q1 * 4);

#pragma unroll 1
    for (int kc = 0; kc < 16; kc++) {
        __syncthreads();   // WT free (previous chunk consumed / prior user done)
        *reinterpret_cast<uint4*>(wtH + n0 * WSTR + q0 * 4) = rh[0];
        *reinterpret_cast<uint4*>(wtH + n1 * WSTR + q1 * 4) = rh[1];
        *reinterpret_cast<uint4*>(wtL + n0 * WSTR + q0 * 4) = rl[0];
        *reinterpret_cast<uint4*>(wtL + n1 * WSTR + q1 * 4) = rl[1];
        __syncthreads();   // WT ready

        // prefetch next chunk (overlaps with MMAs below)
        int kn = (kc < 15) ? kc + 1 : 15;
        rh[0] = *reinterpret_cast<const uint4*>(gwh + n0 * 128 + kn * 8 + q0 * 4);
        rh[1] = *reinterpret_cast<const uint4*>(gwh + n1 * 128 + kn * 8 + q1 * 4);
        rl[0] = *reinterpret_cast<const uint4*>(gwl + n0 * 128 + kn * 8 + q0 * 4);
        rl[1] = *reinterpret_cast<const uint4*>(gwl + n1 * 128 + kn * 8 + q1 * 4);

        uint32_t a0 = xha[kc * 8],                 a1 = xha[kc * 8 + 8 * XSTR];
        uint32_t a2 = xha[kc * 8 + 4],             a3 = xha[kc * 8 + 4 + 8 * XSTR];
        uint32_t l0 = xla[kc * 8],                 l1 = xla[kc * 8 + 8 * XSTR];
        uint32_t l2 = xla[kc * 8 + 4],             l3 = xla[kc * 8 + 4 + 8 * XSTR];

#pragma unroll
        for (int nf = 0; nf < 16; nf++) {
            int nb = (warpN * 128 + nf * 8 + gid) * WSTR + tg;
            uint32_t b0 = wtH[nb], b1 = wtH[nb + 4];
            uint32_t c0 = wtL[nb], c1 = wtL[nb + 4];
            MMA16816(acc[nf], a0, a1, a2, a3, b0, b1);   // Ah * Bh
            MMA16816(acc[nf], l0, l1, l2, l3, b0, b1);   // Al * Bh
            MMA16816(acc[nf], a0, a1, a2, a3, c0, c1);   // Ah * Bl
        }
    }
    __syncthreads();
}

// ---------------------------------------------------------------------------
// Main fused kernel. grid = 2048 (b*4 + wh*2 + ww), block = 256.
// ---------------------------------------------------------------------------
__global__ __launch_bounds__(256, 1)
void swin_kernel(const float* __restrict__ img,
                 const float* __restrict__ bq, const float* __restrict__ bk,
                 const float* __restrict__ bv, const float* __restrict__ bo,
                 const float* __restrict__ logit_scale,
                 float* __restrict__ out)
{
    extern __shared__ float sm[];
    uint32_t* XH = (uint32_t*)(sm + OFF_XH);
    uint32_t* XL = (uint32_t*)(sm + OFF_XL);
    float*    V  = sm + OFF_XH;           // V fp32 overlays XH/XL
    float*    Q  = sm + OFF_Q;            // Q -> O fp32
    float*    K  = sm + OFF_K;
    uint32_t* OH = (uint32_t*)(sm + OFF_OH);   // overlays K
    uint32_t* OL = (uint32_t*)(sm + OFF_OL);
    uint32_t* WTH = (uint32_t*)(sm + OFF_WTH);
    uint32_t* WTL = (uint32_t*)(sm + OFF_WTL);
    float*    TAB = sm + OFF_WTH;         // bias table overlays WT during attention
    int*      GID = (int*)(sm + OFF_GID);

    const int t    = threadIdx.x;
    const int lane = t & 31;
    const int warp = t >> 5;
    const int warpM = warp & 3, warpN = warp >> 2;
    const int gid = lane >> 2, tg = lane & 3;
    const int blk = blockIdx.x;
    const int b   = blk >> 2;
    const int wh  = (blk >> 1) & 1, ww = blk & 1;

    // ---- load shifted window and split to bf16 hi/lo pairs
    const float* imgb = img + (size_t)b * (16 * 16 * 256);
#pragma unroll
    for (int i = 0; i < 16; i++) {
        int f = i * 256 + t;            // float4 index
        int tok = f >> 6, c4 = f & 63;
        int r = tok >> 3, c = tok & 7;
        int ih = (wh * 8 + r + 12) & 15;
        int iw = (ww * 8 + c + 12) & 15;
        float4 v = *reinterpret_cast<const float4*>(&imgb[(ih * 16 + iw) * 256 + c4 * 4]);
        uint32_t h0, l0, h1, l1;
        split2(v.x, v.y, h0, l0);
        split2(v.z, v.w, h1, l1);
        XH[tok * XSTR + 2 * c4]     = h0;
        XH[tok * XSTR + 2 * c4 + 1] = h1;
        XL[tok * XSTR + 2 * c4]     = l0;
        XL[tok * XSTR + 2 * c4 + 1] = l1;
    }
    if (t < 64) {  // token shift-mask group ids
        int r = t >> 3, c = t & 7;
        int gh = wh * 8 + r, gw = ww * 8 + c;
        int hg = (gh < 8) ? 0 : (gh < 12 ? 1 : 2);
        int wg = (gw < 8) ? 0 : (gw < 12 ? 1 : 2);
        GID[t] = hg * 3 + wg;
    }
    // no explicit sync needed: gemm_mma's internal barriers precede A-frag reads

    float acc[16][4];

    // ---- Q = x @ wq^T + bq
    gemm_mma(XH, XL, g_wh + 0 * 32768, g_wl + 0 * 32768, WTH, WTL, acc, warpM, warpN, lane, t);
    {
        int r = warpM * 16 + gid;
#pragma unroll
        for (int nf = 0; nf < 16; nf++) {
            int c = warpN * 128 + nf * 8 + 2 * tg;
            Q[r * FSTR + c]           = acc[nf][0] + bq[c];
            Q[r * FSTR + c + 1]       = acc[nf][1] + bq[c + 1];
            Q[(r + 8) * FSTR + c]     = acc[nf][2] + bq[c];
            Q[(r + 8) * FSTR + c + 1] = acc[nf][3] + bq[c + 1];
        }
    }

    // ---- K = x @ wk^T + bk
    gemm_mma(XH, XL, g_wh + 1 * 32768, g_wl + 1 * 32768, WTH, WTL, acc, warpM, warpN, lane, t);
    {
        int r = warpM * 16 + gid;
#pragma unroll
        for (int nf = 0; nf < 16; nf++) {
            int c = warpN * 128 + nf * 8 + 2 * tg;
            K[r * FSTR + c]           = acc[nf][0] + bk[c];
            K[r * FSTR + c + 1]       = acc[nf][1] + bk[c + 1];
            K[(r + 8) * FSTR + c]     = acc[nf][2] + bk[c];
            K[(r + 8) * FSTR + c + 1] = acc[nf][3] + bk[c + 1];
        }
    }

    // ---- V = x @ wv^T + bv  (overwrites XH/XL region; gemm ends with sync)
    gemm_mma(XH, XL, g_wh + 2 * 32768, g_wl + 2 * 32768, WTH, WTL, acc, warpM, warpN, lane, t);
    {
        int r = warpM * 16 + gid;
#pragma unroll
        for (int nf = 0; nf < 16; nf++) {
            int c = warpN * 128 + nf * 8 + 2 * tg;
            V[r * FSTR + c]           = acc[nf][0] + bv[c];
            V[r * FSTR + c + 1]       = acc[nf][1] + bv[c + 1];
            V[(r + 8) * FSTR + c]     = acc[nf][2] + bv[c];
            V[(r + 8) * FSTR + c + 1] = acc[nf][3] + bv[c + 1];
        }
    }
    __syncthreads();

    // ---- normalize Q (fold per-head scale) and K; copy bias table into WT
#pragma unroll 1
    for (int p = t; p < 1024; p += 256) {
        int mat = p >> 9;           // 0 = Q, 1 = K
        int h   = (p >> 6) & 7;
        int n   = p & 63;
        float* row = (mat ? K : Q) + n * FSTR + h * 32;
        float ss = 0.f;
#pragma unroll
        for (int k = 0; k < 32; k++) ss += row[k] * row[k];
        float sc = 1.f / fmaxf(sqrtf(ss), 1e-12f);
        if (mat == 0) sc *= expf(fminf(logit_scale[h], 4.6051702f)); // ln(100)
#pragma unroll
        for (int k = 0; k < 32; k++) row[k] *= sc;
    }
    for (int i = t; i < 1800; i += 256) TAB[i] = g_tab[i];
    __syncthreads();

    // ---- attention, register-resident probs, no block barriers in head loop.
    // thread (n, mg): row n, key subset m = mg + 4*mm.
    {
        const int n  = t >> 2;
        const int mg = t & 3;
        const int rn = n >> 3, cn = n & 7;
        const int gidn = GID[n];
        const float NEG_INF = __int_as_float(0xff800000);

#pragma unroll 1
        for (int h = 0; h < 8; h++) {
            float4 qv[8];
            const float4* qrow = reinterpret_cast<const float4*>(Q + n * FSTR + h * 32);
#pragma unroll
            for (int i = 0; i < 8; i++) qv[i] = qrow[i];

            float p[16];
#pragma unroll
            for (int mm = 0; mm < 16; mm++) {
                int m = mg + 4 * mm;
                const float4* krow = reinterpret_cast<const float4*>(K + m * FSTR + h * 32);
                float d = 0.f;
#pragma unroll
                for (int i = 0; i < 8; i++) {
                    float4 kv = krow[i];
                    d = fmaf(qv[i].x, kv.x, d);
                    d = fmaf(qv[i].y, kv.y, d);
                    d = fmaf(qv[i].z, kv.z, d);
                    d = fmaf(qv[i].w, kv.w, d);
                }
                int rm = m >> 3, cm = m & 7;
                int tix = ((rn - rm + 7) * 15 + (cn - cm + 7)) * 8 + h;
                p[mm] = (gidn == GID[m]) ? (d + TAB[tix]) : NEG_INF;
            }
            float mx = NEG_INF;
#pragma unroll
            for (int mm = 0; mm < 16; mm++) mx = fmaxf(mx, p[mm]);
            mx = fmaxf(mx, __shfl_xor_sync(0xffffffffu, mx, 1));
            mx = fmaxf(mx, __shfl_xor_sync(0xffffffffu, mx, 2));
            float s = 0.f;
#pragma unroll
            for (int mm = 0; mm < 16; mm++) { p[mm] = expf(p[mm] - mx); s += p[mm]; }
            s += __shfl_xor_sync(0xffffffffu, s, 1);
            s += __shfl_xor_sync(0xffffffffu, s, 2);
            float inv = 1.f / s;

            // partial P*V over this thread's 16 keys, all 32 head-cols
            float o[32];
#pragma unroll
            for (int c = 0; c < 32; c++) o[c] = 0.f;
#pragma unroll
            for (int mm = 0; mm < 16; mm++) {
                int m = mg + 4 * mm;
                float pm = p[mm];
                const float4* vrow = reinterpret_cast<const float4*>(V + m * FSTR + h * 32);
#pragma unroll
                for (int i = 0; i < 8; i++) {
                    float4 vv = vrow[i];
                    o[4 * i + 0] = fmaf(pm, vv.x, o[4 * i + 0]);
                    o[4 * i + 1] = fmaf(pm, vv.y, o[4 * i + 1]);
                    o[4 * i + 2] = fmaf(pm, vv.z, o[4 * i + 2]);
                    o[4 * i + 3] = fmaf(pm, vv.w, o[4 * i + 3]);
                }
            }
            // quad butterfly reduction -> full sums in all 4 lanes
#pragma unroll
            for (int c = 0; c < 32; c++) {
                o[c] += __shfl_xor_sync(0xffffffffu, o[c], 1);
                o[c] += __shfl_xor_sync(0xffffffffu, o[c], 2);
            }
            __syncwarp();   // quad-mates' Q-col reads complete before overwrite
#pragma unroll
            for (int j = 0; j < 8; j++)
                Q[n * FSTR + h * 32 + mg * 8 + j] = o[mg * 8 + j] * inv;  // Q becomes O
        }
    }
    __syncthreads();

    // ---- split O to bf16 hi/lo (into dead K region)
#pragma unroll
    for (int i = 0; i < 16; i++) {
        int f = i * 256 + t;
        int tok = f >> 6, c4 = f & 63;
        float4 v = *reinterpret_cast<const float4*>(&Q[tok * FSTR + c4 * 4]);
        uint32_t h0, l0, h1, l1;
        split2(v.x, v.y, h0, l0);
        split2(v.z, v.w, h1, l1);
        OH[tok * XSTR + 2 * c4]     = h0;
        OH[tok * XSTR + 2 * c4 + 1] = h1;
        OL[tok * XSTR + 2 * c4]     = l0;
        OL[tok * XSTR + 2 * c4 + 1] = l1;
    }

    // ---- Z = O @ wo^T + bo, scattered to output with inverse cyclic shift
    gemm_mma(OH, OL, g_wh + 3 * 32768, g_wl + 3 * 32768, WTH, WTL, acc, warpM, warpN, lane, t);
    {
        int r0 = warpM * 16 + gid;
        int r1 = r0 + 8;
        int rr0 = r0 >> 3, cc0 = r0 & 7;
        int rr1 = r1 >> 3, cc1 = r1 & 7;
        int oh0 = (wh * 8 + rr0 + 12) & 15, ow0 = (ww * 8 + cc0 + 12) & 15;
        int oh1 = (wh * 8 + rr1 + 12) & 15, ow1 = (ww * 8 + cc1 + 12) & 15;
        float* d0 = out + ((size_t)(b * 16 + oh0) * 16 + ow0) * 256;
        float* d1 = out + ((size_t)(b * 16 + oh1) * 16 + ow1) * 256;
#pragma unroll
        for (int nf = 0; nf < 16; nf++) {
            int c = warpN * 128 + nf * 8 + 2 * tg;
            float2 z0 = {acc[nf][0] + bo[c], acc[nf][1] + bo[c + 1]};
            float2 z1 = {acc[nf][2] + bo[c], acc[nf][3] + bo[c + 1]};
            *reinterpret_cast<float2*>(&d0[c]) = z0;
            *reinterpret_cast<float2*>(&d1[c]) = z1;
        }
    }
}

// ---------------------------------------------------------------------------
extern "C" void kernel_launch(void* const* d_in, const int* in_sizes, int n_in,
                              void* d_out, int out_size)
{
    const float* img = (const float*)d_in[0];
    const float* wq  = (const float*)d_in[1];
    const float* bq  = (const float*)d_in[2];
    const float* wk  = (const float*)d_in[3];
    const float* bk  = (const float*)d_in[4];
    const float* wv  = (const float*)d_in[5];
    const float* bv  = (const float*)d_in[6];
    const float* wo  = (const float*)d_in[7];
    const float* bo  = (const float*)d_in[8];
    const float* ls  = (const float*)d_in[9];
    const float* cw1 = (const float*)d_in[10];
    const float* cb1 = (const float*)d_in[11];
    const float* cw2 = (const float*)d_in[12];
    (void)in_sizes; (void)n_in; (void)out_size;

    cudaFuncSetAttribute(swin_kernel,
                         cudaFuncAttributeMaxDynamicSharedMemorySize,
                         SMEM_U32 * 4);

    cpb_kernel<<<225, 256>>>(cw1, cb1, cw2);
    wsplit_kernel<<<64, 256>>>(wq, wk, wv, wo);
    swin_kernel<<<2048, 256, SMEM_U32 * 4>>>(img, bq, bk, bv, bo, ls,
                                             (float*)d_out);
}